// round 1
// baseline (speedup 1.0000x reference)
#include <cuda_runtime.h>
#include <math.h>
#include <float.h>

// ---------------- problem constants ----------------
constexpr int N  = 8;
constexpr int C  = 64;
constexpr int T  = 256;
constexpr int VQ = 90;
constexpr int VK = 50;
constexpr int S  = 4;
constexpr int L  = 4;
constexpr int TQ = T - L;        // 252
constexpr int SC = S * C;        // 256
constexpr int MQ = TQ * VQ;      // 22680  (cols of q projection)
constexpr int MK = T * VK;       // 12800  (cols of k/v projection)
constexpr int MO = T * VQ;       // 23040  (cols of out/down projection)

// ---------------- scratch (device globals; no allocation allowed) ----------------
__device__ float g_q[N * SC * MQ];                 // [n][sc][t<TQ][u]
__device__ float g_k[N * SC * MK];                 // [n][sc][t][v]
__device__ float g_v[N * C  * MK];                 // [n][c][t][v]
__device__ float g_y[N * SC * MO];                 // [n][sc][t][vq]
__device__ float g_yp[N * C * MO];                 // conv-out pre-BN
__device__ float g_dp[N * C * MO];                 // down pre-BN
__device__ float g_att_raw[(L + 1) * N * S * VQ * VK];
__device__ float g_att[N * S * VQ * VK];
__device__ float g_stats[4 * C];                   // sum_y, sumsq_y, sum_d, sumsq_d

// ---------------- zero init for accumulated buffers ----------------
__global__ void zero_kernel() {
    int i = blockIdx.x * blockDim.x + threadIdx.x;
    if (i < (L + 1) * N * S * VQ * VK) g_att_raw[i] = 0.f;
    if (i < 4 * C) g_stats[i] = 0.f;
}

// ---------------- generic conv1x1 GEMM: OUT[n] = W(CO x CIN) @ X[n](CIN x M) + b ----
// X row k starts at X + n*xBatch + k*xRow, valid cols [0, M). OUT row stride = M.
template <int CO, int CIN>
__global__ __launch_bounds__(256) void proj_gemm(
    const float* __restrict__ X, const float* __restrict__ W,
    const float* __restrict__ b, float* __restrict__ OUT,
    int M, int xRow, long long xBatch, long long oBatch)
{
    constexpr int BO = 64, BC = 96, KT = 16;
    __shared__ float Ws[KT][BO + 1];
    __shared__ float Xs[KT][BC + 1];

    const int n  = blockIdx.z;
    const int o0 = blockIdx.y * BO;
    const int c0 = blockIdx.x * BC;
    const float* Xn = X + (long long)n * xBatch;
    float* On = OUT + (long long)n * oBatch;

    const int tid  = threadIdx.x;
    const int colT = tid & 15;   // 16 groups of 6 cols
    const int oT   = tid >> 4;   // 16 groups of 4 outs
    float acc[4][6];
#pragma unroll
    for (int i = 0; i < 4; i++)
#pragma unroll
        for (int j = 0; j < 6; j++) acc[i][j] = 0.f;

    for (int k0 = 0; k0 < CIN; k0 += KT) {
        for (int idx = tid; idx < KT * BO; idx += 256) {
            int kk = idx % KT, oo = idx / KT;
            Ws[kk][oo] = W[(o0 + oo) * CIN + k0 + kk];
        }
        for (int idx = tid; idx < KT * BC; idx += 256) {
            int kk = idx / BC, cc = idx % BC;
            int col = c0 + cc;
            Xs[kk][cc] = (col < M) ? Xn[(long long)(k0 + kk) * xRow + col] : 0.f;
        }
        __syncthreads();
#pragma unroll
        for (int kk = 0; kk < KT; kk++) {
            float wv[4], xv[6];
#pragma unroll
            for (int i = 0; i < 4; i++) wv[i] = Ws[kk][oT * 4 + i];
#pragma unroll
            for (int j = 0; j < 6; j++) xv[j] = Xs[kk][colT * 6 + j];
#pragma unroll
            for (int i = 0; i < 4; i++)
#pragma unroll
                for (int j = 0; j < 6; j++) acc[i][j] += wv[i] * xv[j];
        }
        __syncthreads();
    }
#pragma unroll
    for (int i = 0; i < 4; i++) {
        int o = o0 + oT * 4 + i;
        float bias = b[o];
#pragma unroll
        for (int j = 0; j < 6; j++) {
            int col = c0 + colT * 6 + j;
            if (col < M) On[(long long)o * M + col] = acc[i][j] + bias;
        }
    }
}

// ---------------- multi-lag attention scores -------------------------------------
// att_raw[l][n][s][u][v] += sum_{c,t} q[n,s,c,t,u] * k[n,s,c,t+l,v]  (scaled)
// grid: (N*S, L+1, 2 c-chunks of 32), block 192 (180 active), micro-tile 5u x 5v.
__global__ __launch_bounds__(192) void att_kernel() {
    constexpr int TT = 12;                       // 252 = 21 * 12
    __shared__ float qs[TT][VQ];
    __shared__ float ks[TT][VK];

    const int ns = blockIdx.x, l = blockIdx.y, chunk = blockIdx.z;
    const int n = ns / S, s = ns % S;
    const int tid = threadIdx.x;
    const bool active = tid < 180;
    const int u0 = (tid / 10) * 5;
    const int v0 = (tid % 10) * 5;

    float acc[5][5];
#pragma unroll
    for (int i = 0; i < 5; i++)
#pragma unroll
        for (int j = 0; j < 5; j++) acc[i][j] = 0.f;

    const float* qb = g_q + (long long)(n * SC + s * C) * MQ;
    const float* kb = g_k + (long long)(n * SC + s * C) * MK;

    for (int c = chunk * 32; c < chunk * 32 + 32; c++) {
        const float* qc = qb + (long long)c * MQ;
        const float* kc = kb + (long long)c * MK + l * VK;   // rows shifted by lag
        for (int t0 = 0; t0 < TQ; t0 += TT) {
            for (int idx = tid; idx < TT * VQ; idx += 192) {
                int tt = idx / VQ, uu = idx % VQ;
                qs[tt][uu] = qc[(t0 + tt) * VQ + uu];
            }
            for (int idx = tid; idx < TT * VK; idx += 192) {
                int tt = idx / VK, vv = idx % VK;
                ks[tt][vv] = kc[(t0 + tt) * VK + vv];
            }
            __syncthreads();
            if (active) {
#pragma unroll
                for (int tt = 0; tt < TT; tt++) {
                    float qv[5], kv[5];
#pragma unroll
                    for (int i = 0; i < 5; i++) qv[i] = qs[tt][u0 + i];
#pragma unroll
                    for (int j = 0; j < 5; j++) kv[j] = ks[tt][v0 + j];
#pragma unroll
                    for (int i = 0; i < 5; i++)
#pragma unroll
                        for (int j = 0; j < 5; j++) acc[i][j] += qv[i] * kv[j];
                }
            }
            __syncthreads();
        }
    }
    if (active) {
        const float inv_scale = rsqrtf((float)(C * TQ));
        float* outp = g_att_raw + ((long long)(l * N + n) * S + s) * VQ * VK;
#pragma unroll
        for (int i = 0; i < 5; i++)
#pragma unroll
            for (int j = 0; j < 5; j++)
                atomicAdd(&outp[(u0 + i) * VK + (v0 + j)], acc[i][j] * inv_scale);
    }
}

// ---------------- (max+mean)/2 over lags, softmax over v --------------------------
__global__ void softmax_kernel() {
    const int warp = (blockIdx.x * blockDim.x + threadIdx.x) >> 5;
    const int lane = threadIdx.x & 31;
    if (warp >= N * S * VQ) return;
    const int RS = N * S * VQ * VK;

    float p[2];
#pragma unroll
    for (int h = 0; h < 2; h++) {
        int v = lane + h * 32;
        p[h] = -FLT_MAX;
        if (v < VK) {
            float m = -FLT_MAX, sm = 0.f;
#pragma unroll
            for (int l = 0; l <= L; l++) {
                float a = g_att_raw[l * RS + warp * VK + v];
                m = fmaxf(m, a);
                sm += a;
            }
            p[h] = 0.5f * (m + sm * (1.0f / (L + 1)));
        }
    }
    float rmax = fmaxf(p[0], p[1]);
#pragma unroll
    for (int o = 16; o; o >>= 1) rmax = fmaxf(rmax, __shfl_xor_sync(0xffffffffu, rmax, o));
    float e[2], ssum = 0.f;
#pragma unroll
    for (int h = 0; h < 2; h++) {
        int v = lane + h * 32;
        e[h] = (v < VK) ? expf(p[h] - rmax) : 0.f;
        ssum += e[h];
    }
#pragma unroll
    for (int o = 16; o; o >>= 1) ssum += __shfl_xor_sync(0xffffffffu, ssum, o);
    float inv = 1.f / ssum;
#pragma unroll
    for (int h = 0; h < 2; h++) {
        int v = lane + h * 32;
        if (v < VK) g_att[warp * VK + v] = e[h] * inv;
    }
}

// ---------------- y[n,s,c,t,vq] = sum_u att[n,s,vq,u] * v[n,c,t,u] ----------------
// GEMM per (n,s): rows r=(c*T+t) of v[n] (contiguous, K=50) times att^T (90x50).
// grid: (C*T/128, N*S), block 256 (240 active), micro-tile 8r x 6vq.
__global__ __launch_bounds__(256) void y_kernel() {
    constexpr int BR = 128;
    __shared__ float As[BR][VK + 1];
    __shared__ float Bs[VQ][VK + 1];

    const int ns = blockIdx.y, n = ns / S, s = ns % S;
    const int r0 = blockIdx.x * BR;
    const int tid = threadIdx.x;

    const float* attb = g_att + (long long)ns * VQ * VK;
    for (int idx = tid; idx < VQ * VK; idx += 256) Bs[idx / VK][idx % VK] = attb[idx];
    const float* vb = g_v + (long long)n * C * MK + (long long)r0 * VK;
    for (int idx = tid; idx < BR * VK; idx += 256) As[idx / VK][idx % VK] = vb[idx];
    __syncthreads();

    if (tid < 240) {
        const int rr0  = (tid / 15) * 8;
        const int vq0  = (tid % 15) * 6;
        float acc[8][6];
#pragma unroll
        for (int i = 0; i < 8; i++)
#pragma unroll
            for (int j = 0; j < 6; j++) acc[i][j] = 0.f;
#pragma unroll 2
        for (int kk = 0; kk < VK; kk++) {
            float av[8], bv[6];
#pragma unroll
            for (int i = 0; i < 8; i++) av[i] = As[rr0 + i][kk];
#pragma unroll
            for (int j = 0; j < 6; j++) bv[j] = Bs[vq0 + j][kk];
#pragma unroll
            for (int i = 0; i < 8; i++)
#pragma unroll
                for (int j = 0; j < 6; j++) acc[i][j] += av[i] * bv[j];
        }
        float* yb = g_y + (long long)(n * SC + s * C) * MO + (long long)r0 * VQ;
#pragma unroll
        for (int i = 0; i < 8; i++)
#pragma unroll
            for (int j = 0; j < 6; j++)
                yb[(long long)(rr0 + i) * VQ + vq0 + j] = acc[i][j];
    }
}

// ---------------- BN statistics (sum, sumsq per channel, both paths) --------------
__global__ void stats_kernel() {
    const int co = blockIdx.x, n = blockIdx.y;
    const float* a = g_yp + (long long)(n * C + co) * MO;
    const float* d = g_dp + (long long)(n * C + co) * MO;
    float s1 = 0, s2 = 0, s3 = 0, s4 = 0;
    for (int i = threadIdx.x; i < MO; i += blockDim.x) {
        float x = a[i]; s1 += x; s2 += x * x;
        float z = d[i]; s3 += z; s4 += z * z;
    }
#pragma unroll
    for (int o = 16; o; o >>= 1) {
        s1 += __shfl_xor_sync(0xffffffffu, s1, o);
        s2 += __shfl_xor_sync(0xffffffffu, s2, o);
        s3 += __shfl_xor_sync(0xffffffffu, s3, o);
        s4 += __shfl_xor_sync(0xffffffffu, s4, o);
    }
    __shared__ float sm[8][4];
    int wid = threadIdx.x >> 5, lane = threadIdx.x & 31;
    if (lane == 0) { sm[wid][0] = s1; sm[wid][1] = s2; sm[wid][2] = s3; sm[wid][3] = s4; }
    __syncthreads();
    if (threadIdx.x == 0) {
        float t1 = 0, t2 = 0, t3 = 0, t4 = 0;
        for (int w = 0; w < 8; w++) { t1 += sm[w][0]; t2 += sm[w][1]; t3 += sm[w][2]; t4 += sm[w][3]; }
        atomicAdd(&g_stats[co],           t1);
        atomicAdd(&g_stats[C + co],       t2);
        atomicAdd(&g_stats[2 * C + co],   t3);
        atomicAdd(&g_stats[3 * C + co],   t4);
    }
}

// ---------------- BN + add + leaky_relu ------------------------------------------
__global__ void final_kernel(const float* __restrict__ go, const float* __restrict__ bo,
                             const float* __restrict__ gd, const float* __restrict__ bd,
                             float* __restrict__ out) {
    long long i = (long long)blockIdx.x * blockDim.x + threadIdx.x;
    if (i >= (long long)N * C * MO) return;
    int co = (int)((i / MO) % C);
    const float cnt = (float)N * (float)MO;
    float my = g_stats[co] / cnt;
    float vy = g_stats[C + co] / cnt - my * my;
    float md = g_stats[2 * C + co] / cnt;
    float vd = g_stats[3 * C + co] / cnt - md * md;
    float y = (g_yp[i] - my) * rsqrtf(vy + 1e-5f) * go[co] + bo[co];
    float d = (g_dp[i] - md) * rsqrtf(vd + 1e-5f) * gd[co] + bd[co];
    float z = y + d;
    out[i] = z > 0.f ? z : 0.1f * z;
}

// ---------------- launch -----------------------------------------------------------
extern "C" void kernel_launch(void* const* d_in, const int* in_sizes, int n_in,
                              void* d_out, int out_size) {
    const float* x_q   = (const float*)d_in[0];
    const float* x_k   = (const float*)d_in[1];
    const float* x_v   = (const float*)d_in[2];
    const float* Wq    = (const float*)d_in[3];
    const float* bq    = (const float*)d_in[4];
    const float* Wk    = (const float*)d_in[5];
    const float* bk    = (const float*)d_in[6];
    const float* Wv    = (const float*)d_in[7];
    const float* bv    = (const float*)d_in[8];
    const float* Wout  = (const float*)d_in[9];
    const float* bout  = (const float*)d_in[10];
    const float* g_out = (const float*)d_in[11];
    const float* b_out = (const float*)d_in[12];
    const float* Wdown = (const float*)d_in[13];
    const float* bdown = (const float*)d_in[14];
    const float* g_dn  = (const float*)d_in[15];
    const float* b_dn  = (const float*)d_in[16];
    float* out = (float*)d_out;

    float *pq, *pk, *pv, *py, *pyp, *pdp;
    cudaGetSymbolAddress((void**)&pq,  g_q);
    cudaGetSymbolAddress((void**)&pk,  g_k);
    cudaGetSymbolAddress((void**)&pv,  g_v);
    cudaGetSymbolAddress((void**)&py,  g_y);
    cudaGetSymbolAddress((void**)&pyp, g_yp);
    cudaGetSymbolAddress((void**)&pdp, g_dp);

    zero_kernel<<<2813, 256>>>();

    // projections: q (truncated window = contiguous column prefix), k, v
    proj_gemm<SC, C><<<dim3((MQ + 95) / 96, SC / 64, N), 256>>>(
        x_q, Wq, bq, pq, MQ, MO, (long long)C * MO, (long long)SC * MQ);
    proj_gemm<SC, C><<<dim3((MK + 95) / 96, SC / 64, N), 256>>>(
        x_k, Wk, bk, pk, MK, MK, (long long)C * MK, (long long)SC * MK);
    proj_gemm<C, C><<<dim3((MK + 95) / 96, 1, N), 256>>>(
        x_v, Wv, bv, pv, MK, MK, (long long)C * MK, (long long)C * MK);

    // multi-lag scores + softmax
    att_kernel<<<dim3(N * S, L + 1, 2), 192>>>();
    softmax_kernel<<<(N * S * VQ + 7) / 8, 256>>>();

    // y = att @ v, then output conv and down conv
    y_kernel<<<dim3(C * T / 128, N * S), 256>>>();
    proj_gemm<C, SC><<<dim3(MO / 96, 1, N), 256>>>(
        py, Wout, bout, pyp, MO, MO, (long long)SC * MO, (long long)C * MO);
    proj_gemm<C, C><<<dim3(MO / 96, 1, N), 256>>>(
        x_q, Wdown, bdown, pdp, MO, MO, (long long)C * MO, (long long)C * MO);

    // BN stats + fused epilogue
    stats_kernel<<<dim3(C, N), 256>>>();
    final_kernel<<<(N * C * MO + 255) / 256, 256>>>(g_out, b_out, g_dn, b_dn, out);
}

// round 3
// speedup vs baseline: 1.8763x; 1.8763x over previous
#include <cuda_runtime.h>
#include <math.h>
#include <float.h>

typedef unsigned long long u64;

// ---------------- problem constants ----------------
constexpr int N  = 8;
constexpr int C  = 64;
constexpr int T  = 256;
constexpr int VQ = 90;
constexpr int VK = 50;
constexpr int S  = 4;
constexpr int L  = 4;
constexpr int TQ = T - L;        // 252
constexpr int SC = S * C;        // 256
constexpr int MQ = TQ * VQ;      // 22680
constexpr int MK = T * VK;       // 12800
constexpr int MO = T * VQ;       // 23040
constexpr int NS = N * S;        // 32
constexpr int NCHUNK = 8;        // c-chunks in att kernel

// ---------------- scratch (device globals) ----------------
__device__ float g_q[(size_t)N * SC * MQ];
__device__ float g_k[(size_t)N * SC * MK];
__device__ float g_v[(size_t)N * C * MK];
__device__ float g_w2[(size_t)NS * C * MK];     // w2[n,s,o,t,u]
__device__ float g_yp[(size_t)N * C * MO];
__device__ float g_dp[(size_t)N * C * MO];
__device__ float g_att_raw[(size_t)(L + 1) * NS * NCHUNK * VQ * VK];
__device__ float g_att[(size_t)NS * VQ * VK];
__device__ float g_wperm[SC * C];
__device__ float g_stats[4 * C];

// ---------------- f32x2 packed helpers ----------------
__device__ __forceinline__ u64 pack2(float lo, float hi) {
    u64 r; asm("mov.b64 %0, {%1, %2};" : "=l"(r) : "f"(lo), "f"(hi)); return r;
}
__device__ __forceinline__ void fma2(u64& d, u64 a, u64 b) {
    asm("fma.rn.f32x2 %0, %1, %2, %0;" : "+l"(d) : "l"(a), "l"(b));
}
__device__ __forceinline__ float2 unpack2(u64 v) {
    float2 f; asm("mov.b64 {%0, %1}, %2;" : "=f"(f.x), "=f"(f.y) : "l"(v)); return f;
}

// ---------------- small init kernels ----------------
__global__ void zero_kernel() {
    if (threadIdx.x < 4 * C) g_stats[threadIdx.x] = 0.f;
}
__global__ void perm_kernel(const float* __restrict__ Wout) {
    int i = blockIdx.x * 256 + threadIdx.x;
    if (i < SC * C) {
        int row = i / C, cc = i % C;
        int s = row >> 6, o = row & 63;
        g_wperm[i] = Wout[o * SC + s * C + cc];
    }
}

// ---------------- conv1x1 GEMM (packed f32x2) ----------------
// OUT[z] = W[sIdx](CO x CIN) @ X[n](CIN x M) (+ b); z = n*ZS + sIdx.
template <int CO, int CIN>
__global__ __launch_bounds__(256) void proj_gemm(
    const float* __restrict__ X, const float* __restrict__ W,
    const float* __restrict__ b, float* __restrict__ OUT,
    int M, int xRow, long long xBatch, long long oBatch,
    int ZS, int wStride)
{
    constexpr int BO = 64, BC = 256, KT = 16;
    __shared__ __align__(16) u64   Wsd[KT][BO];       // dup pairs (w,w)
    __shared__ __align__(16) float Xs[KT][BC + 4];

    const int z = blockIdx.z;
    const int n = z / ZS;
    const int sIdx = z % ZS;
    const int o0 = blockIdx.y * BO;
    const int c0 = blockIdx.x * BC;
    const float* Xn = X + (long long)n * xBatch;
    const float* Wz = W + (long long)sIdx * wStride;
    float* On = OUT + (long long)z * oBatch;

    const int tid = threadIdx.x;
    const int tx = tid & 31;       // 32 col groups * 8 cols
    const int ty = tid >> 5;       // 8 row groups * 8 outs

    u64 acc[8][4];
#pragma unroll
    for (int i = 0; i < 8; i++)
#pragma unroll
        for (int j = 0; j < 4; j++) acc[i][j] = 0ull;

    for (int k0 = 0; k0 < CIN; k0 += KT) {
#pragma unroll
        for (int idx = tid; idx < KT * BO; idx += 256) {
            int oo = idx & 63, kk = idx >> 6;
            float w = Wz[(o0 + oo) * CIN + k0 + kk];
            Wsd[kk][oo] = pack2(w, w);
        }
#pragma unroll
        for (int idx = tid; idx < KT * (BC / 4); idx += 256) {
            int kk = idx >> 6;             // BC/4 = 64
            int c4 = idx & 63;
            int col = c0 + c4 * 4;
            float4 xv = make_float4(0.f, 0.f, 0.f, 0.f);
            if (col < M) xv = *(const float4*)(Xn + (long long)(k0 + kk) * xRow + col);
            *(float4*)&Xs[kk][c4 * 4] = xv;
        }
        __syncthreads();
#pragma unroll
        for (int kk = 0; kk < KT; kk++) {
            const ulonglong2* wp = (const ulonglong2*)&Wsd[kk][ty * 8];
            ulonglong2 w01 = wp[0], w23 = wp[1], w45 = wp[2], w67 = wp[3];
            u64 wv[8] = {w01.x, w01.y, w23.x, w23.y, w45.x, w45.y, w67.x, w67.y};
            const ulonglong2* xp = (const ulonglong2*)&Xs[kk][tx * 8];
            ulonglong2 x01 = xp[0], x23 = xp[1];
            u64 bv[4] = {x01.x, x01.y, x23.x, x23.y};
#pragma unroll
            for (int i = 0; i < 8; i++)
#pragma unroll
                for (int j = 0; j < 4; j++) fma2(acc[i][j], wv[i], bv[j]);
        }
        __syncthreads();
    }
#pragma unroll
    for (int i = 0; i < 8; i++) {
        int o = o0 + ty * 8 + i;
        float bias = b ? b[o] : 0.f;
        float* orow = On + (long long)o * M + c0 + tx * 8;
        float2 p0 = unpack2(acc[i][0]), p1 = unpack2(acc[i][1]);
        float2 p2 = unpack2(acc[i][2]), p3 = unpack2(acc[i][3]);
        float4 v0 = make_float4(p0.x + bias, p0.y + bias, p1.x + bias, p1.y + bias);
        float4 v1 = make_float4(p2.x + bias, p2.y + bias, p3.x + bias, p3.y + bias);
        int col = c0 + tx * 8;
        if (col < M)     *(float4*)orow       = v0;
        if (col + 4 < M) *(float4*)(orow + 4) = v1;
    }
}

// ---------------- multi-lag attention scores (packed, chunked, no atomics) -------
// partial[l][ns][chunk][u][v] = sum over 8 c's and all t of q*k(shifted), scaled.
__global__ __launch_bounds__(96) void att_kernel() {
    constexpr int TT = 21;                    // 252 = 12 * 21
    __shared__ __align__(16) float qs[TT][VQ];
    __shared__ __align__(16) u64   ksd[TT][VK];

    const int ns = blockIdx.x, l = blockIdx.y, chunk = blockIdx.z;
    const int n = ns >> 2, s = ns & 3;
    const int tid = threadIdx.x;
    const bool active = tid < 90;
    const int u0 = (tid / 10) * 10;           // 9 u-groups of 10 (5 pairs)
    const int v0 = (tid % 10) * 5;            // 10 v-groups of 5

    u64 acc[5][5];
#pragma unroll
    for (int i = 0; i < 5; i++)
#pragma unroll
        for (int j = 0; j < 5; j++) acc[i][j] = 0ull;

    const float* qb = g_q + (size_t)(n * SC + s * C) * MQ;
    const float* kb = g_k + (size_t)(n * SC + s * C) * MK;

    for (int c = chunk * 8; c < chunk * 8 + 8; c++) {
        const float* qc = qb + (size_t)c * MQ;
        const float* kc = kb + (size_t)c * MK + l * VK;   // lag shift
        for (int t0 = 0; t0 < TQ; t0 += TT) {
            const float* qp = qc + t0 * VQ;   // contiguous TT*VQ run
            const float* kp = kc + t0 * VK;   // contiguous TT*VK run
            for (int idx = tid; idx < TT * VQ; idx += 96)
                qs[idx / VQ][idx % VQ] = qp[idx];
            for (int idx = tid; idx < TT * VK; idx += 96) {
                float kv = kp[idx];
                ksd[idx / VK][idx % VK] = pack2(kv, kv);
            }
            __syncthreads();
            if (active) {
#pragma unroll
                for (int tt = 0; tt < TT; tt++) {
                    u64 a[5], bb[5];
#pragma unroll
                    for (int i = 0; i < 5; i++) a[i] = *(const u64*)&qs[tt][u0 + 2 * i];
#pragma unroll
                    for (int j = 0; j < 5; j++) bb[j] = ksd[tt][v0 + j];
#pragma unroll
                    for (int i = 0; i < 5; i++)
#pragma unroll
                        for (int j = 0; j < 5; j++) fma2(acc[i][j], a[i], bb[j]);
                }
            }
            __syncthreads();
        }
    }
    if (active) {
        const float inv_scale = rsqrtf((float)(C * TQ));
        float* outp = g_att_raw + ((size_t)(l * NS + ns) * NCHUNK + chunk) * (VQ * VK);
#pragma unroll
        for (int i = 0; i < 5; i++)
#pragma unroll
            for (int j = 0; j < 5; j++) {
                float2 p = unpack2(acc[i][j]);
                outp[(u0 + 2 * i)     * VK + v0 + j] = p.x * inv_scale;
                outp[(u0 + 2 * i + 1) * VK + v0 + j] = p.y * inv_scale;
            }
    }
}

// ---------------- reduce chunks, (max+mean)/2 over lags, softmax over v ----------
__global__ void softmax_kernel() {
    const int warp = (blockIdx.x * blockDim.x + threadIdx.x) >> 5;
    const int lane = threadIdx.x & 31;
    if (warp >= NS * VQ) return;
    const int ns = warp / VQ, u = warp % VQ;

    float p[2];
#pragma unroll
    for (int h = 0; h < 2; h++) {
        int v = lane + h * 32;
        p[h] = -FLT_MAX;
        if (v < VK) {
            float m = -FLT_MAX, sm = 0.f;
#pragma unroll
            for (int l = 0; l <= L; l++) {
                float a = 0.f;
#pragma unroll
                for (int ch = 0; ch < NCHUNK; ch++)
                    a += g_att_raw[((size_t)(l * NS + ns) * NCHUNK + ch) * (VQ * VK) + u * VK + v];
                m = fmaxf(m, a);
                sm += a;
            }
            p[h] = 0.5f * (m + sm * (1.0f / (L + 1)));
        }
    }
    float rmax = fmaxf(p[0], p[1]);
#pragma unroll
    for (int o = 16; o; o >>= 1) rmax = fmaxf(rmax, __shfl_xor_sync(0xffffffffu, rmax, o));
    float e[2], ssum = 0.f;
#pragma unroll
    for (int h = 0; h < 2; h++) {
        int v = lane + h * 32;
        e[h] = (v < VK) ? expf(p[h] - rmax) : 0.f;
        ssum += e[h];
    }
#pragma unroll
    for (int o = 16; o; o >>= 1) ssum += __shfl_xor_sync(0xffffffffu, ssum, o);
    float inv = 1.f / ssum;
#pragma unroll
    for (int h = 0; h < 2; h++) {
        int v = lane + h * 32;
        if (v < VK) g_att[(size_t)ns * VQ * VK + u * VK + v] = e[h] * inv;
    }
}

// ---------------- yp[n,o,t,vq] = bout[o] + sum_{s,u} att[n,s,vq,u]*w2[n,s,o,t,u] --
__global__ __launch_bounds__(256) void mix_kernel(const float* __restrict__ bout) {
    constexpr int BR = 128, KH = 25;          // VK processed in 2 halves of 25
    __shared__ __align__(16) float Ast[KH][BR + 4];   // w2 transposed [u][row]
    __shared__ __align__(16) u64   Bsd[KH][VQ];       // att dup pairs

    const int n = blockIdx.y;
    const int r0 = blockIdx.x * BR;           // row = o*T + t
    const int o = r0 / T;                     // constant within block (128 | 256)
    const int tid = threadIdx.x;
    const bool act = tid < 240;
    const int rr0 = (tid / 15) * 8;           // 16 row groups of 8 (4 pairs)
    const int vq0 = (tid % 15) * 6;           // 15 vq groups of 6

    u64 acc[4][6];
#pragma unroll
    for (int i = 0; i < 4; i++)
#pragma unroll
        for (int j = 0; j < 6; j++) acc[i][j] = 0ull;

    for (int s = 0; s < S; s++) {
        const float* ab = g_att + (size_t)(n * S + s) * VQ * VK;
        const float* wb = g_w2 + (size_t)(n * S + s) * C * MK + (size_t)r0 * VK;
        for (int h = 0; h < 2; h++) {
            for (int idx = tid; idx < VQ * KH; idx += 256) {
                int vq = idx / KH, uu = idx % KH;
                float a = ab[vq * VK + h * KH + uu];
                Bsd[uu][vq] = pack2(a, a);
            }
            for (int idx = tid; idx < BR * KH; idx += 256) {
                int rr = idx / KH, uu = idx % KH;
                Ast[uu][rr] = wb[rr * VK + h * KH + uu];
            }
            __syncthreads();
            if (act) {
#pragma unroll 5
                for (int uu = 0; uu < KH; uu++) {
                    const ulonglong2* ap = (const ulonglong2*)&Ast[uu][rr0];
                    ulonglong2 a01 = ap[0], a23 = ap[1];
                    u64 av[4] = {a01.x, a01.y, a23.x, a23.y};
                    u64 bv[6];
#pragma unroll
                    for (int j = 0; j < 6; j++) bv[j] = Bsd[uu][vq0 + j];
#pragma unroll
                    for (int i = 0; i < 4; i++)
#pragma unroll
                        for (int j = 0; j < 6; j++) fma2(acc[i][j], av[i], bv[j]);
                }
            }
            __syncthreads();
        }
    }
    if (act) {
        const float bias = bout[o];
        float* yb = g_yp + (size_t)n * C * MO + (size_t)r0 * VQ;
#pragma unroll
        for (int i = 0; i < 4; i++)
#pragma unroll
            for (int j = 0; j < 6; j++) {
                float2 p = unpack2(acc[i][j]);
                yb[(size_t)(rr0 + 2 * i)     * VQ + vq0 + j] = p.x + bias;
                yb[(size_t)(rr0 + 2 * i + 1) * VQ + vq0 + j] = p.y + bias;
            }
    }
}

// ---------------- BN statistics ----------------
__global__ void stats_kernel() {
    const int co = blockIdx.x, n = blockIdx.y;
    const float* a = g_yp + (size_t)(n * C + co) * MO;
    const float* d = g_dp + (size_t)(n * C + co) * MO;
    float s1 = 0, s2 = 0, s3 = 0, s4 = 0;
    for (int i = threadIdx.x; i < MO; i += blockDim.x) {
        float x = a[i]; s1 += x; s2 += x * x;
        float z = d[i]; s3 += z; s4 += z * z;
    }
#pragma unroll
    for (int o = 16; o; o >>= 1) {
        s1 += __shfl_xor_sync(0xffffffffu, s1, o);
        s2 += __shfl_xor_sync(0xffffffffu, s2, o);
        s3 += __shfl_xor_sync(0xffffffffu, s3, o);
        s4 += __shfl_xor_sync(0xffffffffu, s4, o);
    }
    __shared__ float sm[8][4];
    int wid = threadIdx.x >> 5, lane = threadIdx.x & 31;
    if (lane == 0) { sm[wid][0] = s1; sm[wid][1] = s2; sm[wid][2] = s3; sm[wid][3] = s4; }
    __syncthreads();
    if (threadIdx.x == 0) {
        float t1 = 0, t2 = 0, t3 = 0, t4 = 0;
        for (int w = 0; w < 8; w++) { t1 += sm[w][0]; t2 += sm[w][1]; t3 += sm[w][2]; t4 += sm[w][3]; }
        atomicAdd(&g_stats[co],         t1);
        atomicAdd(&g_stats[C + co],     t2);
        atomicAdd(&g_stats[2 * C + co], t3);
        atomicAdd(&g_stats[3 * C + co], t4);
    }
}

// ---------------- BN + add + leaky_relu ----------------
__global__ void final_kernel(const float* __restrict__ go, const float* __restrict__ bo,
                             const float* __restrict__ gd, const float* __restrict__ bd,
                             float* __restrict__ out) {
    long long i = (long long)blockIdx.x * blockDim.x + threadIdx.x;
    if (i >= (long long)N * C * MO) return;
    int co = (int)((i / MO) % C);
    const float cnt = (float)N * (float)MO;
    float my = g_stats[co] / cnt;
    float vy = g_stats[C + co] / cnt - my * my;
    float md = g_stats[2 * C + co] / cnt;
    float vd = g_stats[3 * C + co] / cnt - md * md;
    float y = (g_yp[i] - my) * rsqrtf(vy + 1e-5f) * go[co] + bo[co];
    float d = (g_dp[i] - md) * rsqrtf(vd + 1e-5f) * gd[co] + bd[co];
    float z = y + d;
    out[i] = z > 0.f ? z : 0.1f * z;
}

// ---------------- launch ----------------
extern "C" void kernel_launch(void* const* d_in, const int* in_sizes, int n_in,
                              void* d_out, int out_size) {
    const float* x_q   = (const float*)d_in[0];
    const float* x_k   = (const float*)d_in[1];
    const float* x_v   = (const float*)d_in[2];
    const float* Wq    = (const float*)d_in[3];
    const float* bq    = (const float*)d_in[4];
    const float* Wk    = (const float*)d_in[5];
    const float* bk    = (const float*)d_in[6];
    const float* Wv    = (const float*)d_in[7];
    const float* bv    = (const float*)d_in[8];
    const float* Wout  = (const float*)d_in[9];
    const float* bout  = (const float*)d_in[10];
    const float* g_out = (const float*)d_in[11];
    const float* b_out = (const float*)d_in[12];
    const float* Wdown = (const float*)d_in[13];
    const float* bdown = (const float*)d_in[14];
    const float* g_dn  = (const float*)d_in[15];
    const float* b_dn  = (const float*)d_in[16];
    float* out = (float*)d_out;

    float *pq, *pk, *pv, *pw2, *pyp, *pdp, *pwperm;
    cudaGetSymbolAddress((void**)&pq,    g_q);
    cudaGetSymbolAddress((void**)&pk,    g_k);
    cudaGetSymbolAddress((void**)&pv,    g_v);
    cudaGetSymbolAddress((void**)&pw2,   g_w2);
    cudaGetSymbolAddress((void**)&pyp,   g_yp);
    cudaGetSymbolAddress((void**)&pdp,   g_dp);
    cudaGetSymbolAddress((void**)&pwperm, g_wperm);

    zero_kernel<<<1, 256>>>();
    perm_kernel<<<(SC * C + 255) / 256, 256>>>(Wout);

    // projections: q (truncated window = contiguous column prefix), k, v
    proj_gemm<SC, C><<<dim3((MQ + 255) / 256, SC / 64, N), 256>>>(
        x_q, Wq, bq, pq, MQ, MO, (long long)C * MO, (long long)SC * MQ, 1, 0);
    proj_gemm<SC, C><<<dim3(MK / 256, SC / 64, N), 256>>>(
        x_k, Wk, bk, pk, MK, MK, (long long)C * MK, (long long)SC * MK, 1, 0);
    proj_gemm<C, C><<<dim3(MK / 256, 1, N), 256>>>(
        x_v, Wv, bv, pv, MK, MK, (long long)C * MK, (long long)C * MK, 1, 0);

    // multi-lag scores + softmax
    att_kernel<<<dim3(NS, L + 1, NCHUNK), 96>>>();
    softmax_kernel<<<(NS * VQ) / 8, 256>>>();

    // w2[n,s] = Wperm[s] @ v[n]  (batched over z = n*4+s)
    proj_gemm<C, C><<<dim3(MK / 256, 1, NS), 256>>>(
        pv, pwperm, nullptr, pw2, MK, MK, (long long)C * MK, (long long)C * MK, S, C * C);

    // yp = att-weighted mix of w2 (+bout), and the residual down conv
    mix_kernel<<<dim3(C * T / 128, N), 256>>>(bout);
    proj_gemm<C, C><<<dim3(MO / 256, 1, N), 256>>>(
        x_q, Wdown, bdown, pdp, MO, MO, (long long)C * MO, (long long)C * MO, 1, 0);

    // BN stats + fused epilogue
    stats_kernel<<<dim3(C, N), 256>>>();
    final_kernel<<<((long long)N * C * MO + 255) / 256, 256>>>(g_out, b_out, g_dn, b_dn, out);
}

// round 5
// speedup vs baseline: 2.3474x; 1.2511x over previous
#include <cuda_runtime.h>
#include <math.h>
#include <float.h>

typedef unsigned long long u64;

// ---------------- problem constants ----------------
constexpr int N  = 8;
constexpr int C  = 64;
constexpr int T  = 256;
constexpr int VQ = 90;
constexpr int VK = 50;
constexpr int S  = 4;
constexpr int L  = 4;
constexpr int TQ = T - L;        // 252
constexpr int SC = S * C;        // 256
constexpr int MQ = TQ * VQ;      // 22680
constexpr int MK = T * VK;       // 12800
constexpr int MO = T * VQ;       // 23040
constexpr int NS = N * S;        // 32
constexpr int NCHUNK = 8;        // c-chunks in att kernel

// ---------------- scratch (device globals) ----------------
__device__ float g_q[(size_t)N * SC * MQ];
__device__ float g_k[(size_t)N * SC * MK];
__device__ float g_v[(size_t)N * C * MK];
__device__ float g_w2[(size_t)NS * C * MK];     // w2[n,s,o,t,u]
__device__ float g_yp[(size_t)N * C * MO];
__device__ float g_dp[(size_t)N * C * MO];
__device__ float g_att_raw[(size_t)(L + 1) * NS * NCHUNK * VQ * VK];
__device__ float g_att[(size_t)NS * VQ * VK];
__device__ float g_wperm[SC * C];
__device__ float g_stats[4 * C];

// ---------------- f32x2 packed helpers ----------------
__device__ __forceinline__ u64 pack2(float lo, float hi) {
    u64 r; asm("mov.b64 %0, {%1, %2};" : "=l"(r) : "f"(lo), "f"(hi)); return r;
}
__device__ __forceinline__ u64 dup2(float v) {
    u64 r; asm("mov.b64 %0, {%1, %1};" : "=l"(r) : "f"(v)); return r;
}
__device__ __forceinline__ void fma2(u64& d, u64 a, u64 b) {
    asm("fma.rn.f32x2 %0, %1, %2, %0;" : "+l"(d) : "l"(a), "l"(b));
}
__device__ __forceinline__ float2 unpack2(u64 v) {
    float2 f; asm("mov.b64 {%0, %1}, %2;" : "=f"(f.x), "=f"(f.y) : "l"(v)); return f;
}

// ---------------- small init kernels ----------------
__global__ void zero_kernel() {
    if (threadIdx.x < 4 * C) g_stats[threadIdx.x] = 0.f;
}
__global__ void perm_kernel(const float* __restrict__ Wout) {
    int i = blockIdx.x * 256 + threadIdx.x;
    if (i < SC * C) {
        int row = i / C, cc = i % C;
        int s = row >> 6, o = row & 63;
        g_wperm[i] = Wout[o * SC + s * C + cc];
    }
}

// ---------------- conv1x1 GEMM (packed f32x2, scalar W in smem) ----------------
// OUT[z] = W[sIdx](CO x CIN) @ X[n](CIN x M) (+ b); z = n*ZS + sIdx.
template <int CO, int CIN>
__global__ __launch_bounds__(256, 2) void proj_gemm(
    const float* __restrict__ X, const float* __restrict__ W,
    const float* __restrict__ b, float* __restrict__ OUT,
    int M, int xRow, long long xBatch, long long oBatch,
    int ZS, int wStride)
{
    constexpr int BO = 64, BC = 256, KT = 16;
    __shared__ __align__(16) float Ws[KT][BO];        // scalar weights
    __shared__ __align__(16) float Xs[KT][BC + 4];

    const int z = blockIdx.z;
    const int n = z / ZS;
    const int sIdx = z % ZS;
    const int o0 = blockIdx.y * BO;
    const int c0 = blockIdx.x * BC;
    const float* Xn = X + (long long)n * xBatch;
    const float* Wz = W + (long long)sIdx * wStride;
    float* On = OUT + (long long)z * oBatch;

    const int tid = threadIdx.x;
    const int tx = tid & 31;       // 32 col groups * 8 cols
    const int ty = tid >> 5;       // 8 row groups * 8 outs

    u64 acc[8][4];
#pragma unroll
    for (int i = 0; i < 8; i++)
#pragma unroll
        for (int j = 0; j < 4; j++) acc[i][j] = 0ull;

    for (int k0 = 0; k0 < CIN; k0 += KT) {
#pragma unroll
        for (int idx = tid; idx < KT * BO; idx += 256) {
            int oo = idx & 63, kk = idx >> 6;
            Ws[kk][oo] = Wz[(o0 + oo) * CIN + k0 + kk];
        }
#pragma unroll
        for (int idx = tid; idx < KT * (BC / 4); idx += 256) {
            int kk = idx >> 6;             // BC/4 = 64
            int c4 = idx & 63;
            int col = c0 + c4 * 4;
            float4 xv = make_float4(0.f, 0.f, 0.f, 0.f);
            if (col < M) xv = *(const float4*)(Xn + (long long)(k0 + kk) * xRow + col);
            *(float4*)&Xs[kk][c4 * 4] = xv;
        }
        __syncthreads();
#pragma unroll
        for (int kk = 0; kk < KT; kk++) {
            float4 wa = *(const float4*)&Ws[kk][ty * 8];
            float4 wb = *(const float4*)&Ws[kk][ty * 8 + 4];
            u64 wv[8] = {dup2(wa.x), dup2(wa.y), dup2(wa.z), dup2(wa.w),
                         dup2(wb.x), dup2(wb.y), dup2(wb.z), dup2(wb.w)};
            const ulonglong2* xp = (const ulonglong2*)&Xs[kk][tx * 8];
            ulonglong2 x01 = xp[0], x23 = xp[1];
            u64 bv[4] = {x01.x, x01.y, x23.x, x23.y};
#pragma unroll
            for (int i = 0; i < 8; i++)
#pragma unroll
                for (int j = 0; j < 4; j++) fma2(acc[i][j], wv[i], bv[j]);
        }
        __syncthreads();
    }
#pragma unroll
    for (int i = 0; i < 8; i++) {
        int o = o0 + ty * 8 + i;
        float bias = b ? b[o] : 0.f;
        float* orow = On + (long long)o * M + c0 + tx * 8;
        float2 p0 = unpack2(acc[i][0]), p1 = unpack2(acc[i][1]);
        float2 p2 = unpack2(acc[i][2]), p3 = unpack2(acc[i][3]);
        float4 v0 = make_float4(p0.x + bias, p0.y + bias, p1.x + bias, p1.y + bias);
        float4 v1 = make_float4(p2.x + bias, p2.y + bias, p3.x + bias, p3.y + bias);
        int col = c0 + tx * 8;
        if (col < M)     *(float4*)orow       = v0;
        if (col + 4 < M) *(float4*)(orow + 4) = v1;
    }
}

// ---------------- multi-lag attention scores ----------------
// partial[l][ns][chunk][u][v]; q scalar (dup'd in reg), k natural pairs.
// thread tile: 5 u (scalar) x 10 v (5 pairs). 90 active threads of 96.
__global__ __launch_bounds__(96) void att_kernel() {
    constexpr int TT = 21;                    // 252 = 12 * 21
    constexpr int KP = 52;                    // padded VK pitch (floats)
    __shared__ __align__(16) float qs[TT][VQ];
    __shared__ __align__(16) float ks[TT][KP];

    const int ns = blockIdx.x, l = blockIdx.y, chunk = blockIdx.z;
    const int n = ns >> 2, s = ns & 3;
    const int tid = threadIdx.x;
    const bool active = tid < 90;
    const int u0 = (tid / 5) * 5;             // 18 u-groups of 5 (scalar)
    const int v0 = (tid % 5) * 10;            // 5 v-groups of 10 (5 pairs)

    u64 acc[5][5];
#pragma unroll
    for (int i = 0; i < 5; i++)
#pragma unroll
        for (int j = 0; j < 5; j++) acc[i][j] = 0ull;

    const float* qb = g_q + (size_t)(n * SC + s * C) * MQ;
    const float* kb = g_k + (size_t)(n * SC + s * C) * MK;

    for (int c = chunk * 8; c < chunk * 8 + 8; c++) {
        const float* qc = qb + (size_t)c * MQ;
        const float* kc = kb + (size_t)c * MK + l * VK;   // lag shift
        for (int t0 = 0; t0 < TQ; t0 += TT) {
            const float* qp = qc + t0 * VQ;   // contiguous TT*VQ run
            const float* kp = kc + t0 * VK;   // contiguous TT*VK run
            for (int idx = tid; idx < TT * VQ; idx += 96)
                qs[idx / VQ][idx % VQ] = qp[idx];
            for (int idx = tid; idx < TT * VK; idx += 96)
                ks[idx / VK][idx % VK] = kp[idx];
            __syncthreads();
            if (active) {
#pragma unroll
                for (int tt = 0; tt < TT; tt++) {
                    u64 a[5], bb[5];
#pragma unroll
                    for (int i = 0; i < 5; i++) a[i] = dup2(qs[tt][u0 + i]);
#pragma unroll
                    for (int j = 0; j < 5; j++) bb[j] = *(const u64*)&ks[tt][v0 + 2 * j];
#pragma unroll
                    for (int i = 0; i < 5; i++)
#pragma unroll
                        for (int j = 0; j < 5; j++) fma2(acc[i][j], a[i], bb[j]);
                }
            }
            __syncthreads();
        }
    }
    if (active) {
        const float inv_scale = rsqrtf((float)(C * TQ));
        float* outp = g_att_raw + ((size_t)(l * NS + ns) * NCHUNK + chunk) * (VQ * VK);
#pragma unroll
        for (int i = 0; i < 5; i++)
#pragma unroll
            for (int j = 0; j < 5; j++) {
                float2 p = unpack2(acc[i][j]);
                outp[(u0 + i) * VK + v0 + 2 * j]     = p.x * inv_scale;
                outp[(u0 + i) * VK + v0 + 2 * j + 1] = p.y * inv_scale;
            }
    }
}

// ---------------- reduce chunks, (max+mean)/2 over lags, softmax over v ----------
__global__ void softmax_kernel() {
    const int warp = (blockIdx.x * blockDim.x + threadIdx.x) >> 5;
    const int lane = threadIdx.x & 31;
    if (warp >= NS * VQ) return;
    const int ns = warp / VQ, u = warp % VQ;

    float p[2];
#pragma unroll
    for (int h = 0; h < 2; h++) {
        int v = lane + h * 32;
        p[h] = -FLT_MAX;
        if (v < VK) {
            float m = -FLT_MAX, sm = 0.f;
#pragma unroll
            for (int l = 0; l <= L; l++) {
                float a = 0.f;
#pragma unroll
                for (int ch = 0; ch < NCHUNK; ch++)
                    a += g_att_raw[((size_t)(l * NS + ns) * NCHUNK + ch) * (VQ * VK) + u * VK + v];
                m = fmaxf(m, a);
                sm += a;
            }
            p[h] = 0.5f * (m + sm * (1.0f / (L + 1)));
        }
    }
    float rmax = fmaxf(p[0], p[1]);
#pragma unroll
    for (int o = 16; o; o >>= 1) rmax = fmaxf(rmax, __shfl_xor_sync(0xffffffffu, rmax, o));
    float e[2], ssum = 0.f;
#pragma unroll
    for (int h = 0; h < 2; h++) {
        int v = lane + h * 32;
        e[h] = (v < VK) ? expf(p[h] - rmax) : 0.f;
        ssum += e[h];
    }
#pragma unroll
    for (int o = 16; o; o >>= 1) ssum += __shfl_xor_sync(0xffffffffu, ssum, o);
    float inv = 1.f / ssum;
#pragma unroll
    for (int h = 0; h < 2; h++) {
        int v = lane + h * 32;
        if (v < VK) g_att[(size_t)ns * VQ * VK + u * VK + v] = e[h] * inv;
    }
}

// ---------------- yp[n,o,t,vq] = bout[o] + sum_{s,u} att[n,s,vq,u]*w2[n,s,o,t,u] --
__global__ __launch_bounds__(256, 2) void mix_kernel(const float* __restrict__ bout) {
    constexpr int BR = 128, KH = 25;          // VK processed in 2 halves of 25
    __shared__ __align__(16) float Ast[KH][BR + 4];   // w2 transposed [u][row]
    __shared__ __align__(16) float Bs[KH][VQ + 2];    // att scalar

    const int n = blockIdx.y;
    const int r0 = blockIdx.x * BR;           // row = o*T + t
    const int o = r0 / T;                     // constant within block (128 | 256)
    const int tid = threadIdx.x;
    const bool act = tid < 240;
    const int rr0 = (tid / 15) * 8;           // 16 row groups of 8 (4 pairs)
    const int vq0 = (tid % 15) * 6;           // 15 vq groups of 6

    u64 acc[4][6];
#pragma unroll
    for (int i = 0; i < 4; i++)
#pragma unroll
        for (int j = 0; j < 6; j++) acc[i][j] = 0ull;

    for (int s = 0; s < S; s++) {
        const float* ab = g_att + (size_t)(n * S + s) * VQ * VK;
        const float* wb = g_w2 + (size_t)(n * S + s) * C * MK + (size_t)r0 * VK;
        for (int h = 0; h < 2; h++) {
            for (int idx = tid; idx < VQ * KH; idx += 256) {
                int vq = idx / KH, uu = idx % KH;
                Bs[uu][vq] = ab[vq * VK + h * KH + uu];
            }
            for (int idx = tid; idx < BR * KH; idx += 256) {
                int rr = idx / KH, uu = idx % KH;
                Ast[uu][rr] = wb[rr * VK + h * KH + uu];
            }
            __syncthreads();
            if (act) {
#pragma unroll 5
                for (int uu = 0; uu < KH; uu++) {
                    const ulonglong2* ap = (const ulonglong2*)&Ast[uu][rr0];
                    ulonglong2 a01 = ap[0], a23 = ap[1];
                    u64 av[4] = {a01.x, a01.y, a23.x, a23.y};
                    u64 bv[6];
#pragma unroll
                    for (int j = 0; j < 6; j++) bv[j] = dup2(Bs[uu][vq0 + j]);
#pragma unroll
                    for (int i = 0; i < 4; i++)
#pragma unroll
                        for (int j = 0; j < 6; j++) fma2(acc[i][j], av[i], bv[j]);
                }
            }
            __syncthreads();
        }
    }
    if (act) {
        const float bias = bout[o];
        float* yb = g_yp + (size_t)n * C * MO + (size_t)r0 * VQ;
#pragma unroll
        for (int i = 0; i < 4; i++)
#pragma unroll
            for (int j = 0; j < 6; j++) {
                float2 p = unpack2(acc[i][j]);
                yb[(size_t)(rr0 + 2 * i)     * VQ + vq0 + j] = p.x + bias;
                yb[(size_t)(rr0 + 2 * i + 1) * VQ + vq0 + j] = p.y + bias;
            }
    }
}

// ---------------- BN statistics ----------------
__global__ void stats_kernel() {
    const int co = blockIdx.x, n = blockIdx.y;
    const float* a = g_yp + (size_t)(n * C + co) * MO;
    const float* d = g_dp + (size_t)(n * C + co) * MO;
    float s1 = 0, s2 = 0, s3 = 0, s4 = 0;
    for (int i = threadIdx.x; i < MO; i += blockDim.x) {
        float x = a[i]; s1 += x; s2 += x * x;
        float z = d[i]; s3 += z; s4 += z * z;
    }
#pragma unroll
    for (int o = 16; o; o >>= 1) {
        s1 += __shfl_xor_sync(0xffffffffu, s1, o);
        s2 += __shfl_xor_sync(0xffffffffu, s2, o);
        s3 += __shfl_xor_sync(0xffffffffu, s3, o);
        s4 += __shfl_xor_sync(0xffffffffu, s4, o);
    }
    __shared__ float sm[8][4];
    int wid = threadIdx.x >> 5, lane = threadIdx.x & 31;
    if (lane == 0) { sm[wid][0] = s1; sm[wid][1] = s2; sm[wid][2] = s3; sm[wid][3] = s4; }
    __syncthreads();
    if (threadIdx.x == 0) {
        float t1 = 0, t2 = 0, t3 = 0, t4 = 0;
        for (int w = 0; w < 8; w++) { t1 += sm[w][0]; t2 += sm[w][1]; t3 += sm[w][2]; t4 += sm[w][3]; }
        atomicAdd(&g_stats[co],         t1);
        atomicAdd(&g_stats[C + co],     t2);
        atomicAdd(&g_stats[2 * C + co], t3);
        atomicAdd(&g_stats[3 * C + co], t4);
    }
}

// ---------------- BN + add + leaky_relu ----------------
__global__ void final_kernel(const float* __restrict__ go, const float* __restrict__ bo,
                             const float* __restrict__ gd, const float* __restrict__ bd,
                             float* __restrict__ out) {
    long long i = (long long)blockIdx.x * blockDim.x + threadIdx.x;
    if (i >= (long long)N * C * MO) return;
    int co = (int)((i / MO) % C);
    const float cnt = (float)N * (float)MO;
    float my = g_stats[co] / cnt;
    float vy = g_stats[C + co] / cnt - my * my;
    float md = g_stats[2 * C + co] / cnt;
    float vd = g_stats[3 * C + co] / cnt - md * md;
    float y = (g_yp[i] - my) * rsqrtf(vy + 1e-5f) * go[co] + bo[co];
    float d = (g_dp[i] - md) * rsqrtf(vd + 1e-5f) * gd[co] + bd[co];
    float z = y + d;
    out[i] = z > 0.f ? z : 0.1f * z;
}

// ---------------- launch ----------------
extern "C" void kernel_launch(void* const* d_in, const int* in_sizes, int n_in,
                              void* d_out, int out_size) {
    const float* x_q   = (const float*)d_in[0];
    const float* x_k   = (const float*)d_in[1];
    const float* x_v   = (const float*)d_in[2];
    const float* Wq    = (const float*)d_in[3];
    const float* bq    = (const float*)d_in[4];
    const float* Wk    = (const float*)d_in[5];
    const float* bk    = (const float*)d_in[6];
    const float* Wv    = (const float*)d_in[7];
    const float* bv    = (const float*)d_in[8];
    const float* Wout  = (const float*)d_in[9];
    const float* bout  = (const float*)d_in[10];
    const float* g_out = (const float*)d_in[11];
    const float* b_out = (const float*)d_in[12];
    const float* Wdown = (const float*)d_in[13];
    const float* bdown = (const float*)d_in[14];
    const float* g_dn  = (const float*)d_in[15];
    const float* b_dn  = (const float*)d_in[16];
    float* out = (float*)d_out;

    float *pq, *pk, *pv, *pw2, *pyp, *pdp, *pwperm;
    cudaGetSymbolAddress((void**)&pq,    g_q);
    cudaGetSymbolAddress((void**)&pk,    g_k);
    cudaGetSymbolAddress((void**)&pv,    g_v);
    cudaGetSymbolAddress((void**)&pw2,   g_w2);
    cudaGetSymbolAddress((void**)&pyp,   g_yp);
    cudaGetSymbolAddress((void**)&pdp,   g_dp);
    cudaGetSymbolAddress((void**)&pwperm, g_wperm);

    zero_kernel<<<1, 256>>>();
    perm_kernel<<<(SC * C + 255) / 256, 256>>>(Wout);

    // projections: q (truncated window = contiguous column prefix), k, v
    proj_gemm<SC, C><<<dim3((MQ + 255) / 256, SC / 64, N), 256>>>(
        x_q, Wq, bq, pq, MQ, MO, (long long)C * MO, (long long)SC * MQ, 1, 0);
    proj_gemm<SC, C><<<dim3(MK / 256, SC / 64, N), 256>>>(
        x_k, Wk, bk, pk, MK, MK, (long long)C * MK, (long long)SC * MK, 1, 0);
    proj_gemm<C, C><<<dim3(MK / 256, 1, N), 256>>>(
        x_v, Wv, bv, pv, MK, MK, (long long)C * MK, (long long)C * MK, 1, 0);

    // multi-lag scores + softmax
    att_kernel<<<dim3(NS, L + 1, NCHUNK), 96>>>();
    softmax_kernel<<<(NS * VQ) / 8, 256>>>();

    // w2[n,s] = Wperm[s] @ v[n]  (batched over z = n*4+s)
    proj_gemm<C, C><<<dim3(MK / 256, 1, NS), 256>>>(
        pv, pwperm, nullptr, pw2, MK, MK, (long long)C * MK, (long long)C * MK, S, C * C);

    // yp = att-weighted mix of w2 (+bout), and the residual down conv
    mix_kernel<<<dim3(C * T / 128, N), 256>>>(bout);
    proj_gemm<C, C><<<dim3(MO / 256, 1, N), 256>>>(
        x_q, Wdown, bdown, pdp, MO, MO, (long long)C * MO, (long long)C * MO, 1, 0);

    // BN stats + fused epilogue
    stats_kernel<<<dim3(C, N), 256>>>();
    final_kernel<<<((long long)N * C * MO + 255) / 256, 256>>>(g_out, b_out, g_dn, b_dn, out);
}